// round 7
// baseline (speedup 1.0000x reference)
#include <cuda_runtime.h>
#include <cstdint>

#define B_    16
#define CIN_  64
#define COUT_ 64
#define HH    256
#define WW    256
#define HW    (HH * WW)
#define EPSF  1e-8f

// Demodulated tf32 weights in fragment-consumption order:
// [b][half 0..1][tap 0..8][kk 0..3][coh 0..1][ntp 0..1][lane 0..31][4 words]
// +4096 float pad for depth-2 prefetch overrun past the last sample.
__device__ __align__(16) float g_wt[B_ * 2 * 9 * 4 * 2 * 2 * 32 * 4 + 4096];

__device__ __forceinline__ float f2tf32f(float x) {
    uint32_t r;
    asm("cvt.rna.tf32.f32 %0, %1;" : "=r"(r) : "f"(x));
    return __uint_as_float(r);
}

#define MMA_OP(d, a, b0, b1)                                                  \
    asm volatile(                                                             \
        "mma.sync.aligned.m16n8k8.row.col.f32.tf32.tf32.f32 "                 \
        "{%0,%1,%2,%3},{%4,%5,%6,%7},{%8,%9},{%0,%1,%2,%3};"                  \
        : "+f"((d)[0]), "+f"((d)[1]), "+f"((d)[2]), "+f"((d)[3])              \
        : "r"((a)[0]), "r"((a)[1]), "r"((a)[2]), "r"((a)[3]),                 \
          "r"(b0), "r"(b1))

// ---------------------------------------------------------------------------
// Kernel 1: modulate + demodulate + tf32-round + swizzle into fragment order
// ---------------------------------------------------------------------------
__global__ void modw_kernel(const float* __restrict__ w,
                            const float* __restrict__ y,
                            float* __restrict__ wt) {
    const int co = blockIdx.x;
    const int b  = blockIdx.y;
    const int ci = threadIdx.x;

    const float c  = 1.0f / 24.0f;               // (64*9)^-0.5
    const float yv = y[b * CIN_ + ci] * c;

    float v[9];
    float s = 0.0f;
    const float* wp = w + (co * CIN_ + ci) * 9;
#pragma unroll
    for (int t = 0; t < 9; t++) {
        v[t] = wp[t] * yv;
        s += v[t] * v[t];
    }
#pragma unroll
    for (int off = 16; off > 0; off >>= 1)
        s += __shfl_down_sync(0xffffffffu, s, off);
    __shared__ float ps[2];
    if ((ci & 31) == 0) ps[ci >> 5] = s;
    __syncthreads();
    const float d = rsqrtf(ps[0] + ps[1] + EPSF);

    const int half = ci >> 5;
    const int kk   = (ci >> 3) & 3;
    const int k    = ci & 7;
    const int p    = k & 3;
    const int sgm  = k >> 2;
    const int coh  = co >> 5;
    const int cot  = (co >> 3) & 3;
    const int ntp  = cot >> 1;
    const int nto  = cot & 1;
    const int lane = (co & 7) * 4 + p;
    const int word = nto * 2 + sgm;

#pragma unroll
    for (int t = 0; t < 9; t++) {
        const size_t idx =
            ((((((size_t)((b * 2 + half) * 9 + t) * 4 + kk) * 2 + coh) * 2 + ntp)
              * 32 + lane) * 4) + word;
        wt[idx] = f2tf32f(v[t] * d);
    }
}

// ---------------------------------------------------------------------------
// Kernel 2: tf32 mma.sync implicit-GEMM conv, M32 x N32 warp tile.
// CIN split into 2 halves of 32 staged sequentially.
// X layout pair-interleaved: xs[pp 0..15][r 0..3][c 0..65][s 0..1],
//   pp = (ci>>3)*4 + (ci&3), s = (ci>>2)&1; pp stride 536 words (pad 8)
//   -> A fragment = 4 conflict-free LDS.64 per kk.
// B loaded straight from gmem (fragment order) with DEPTH-2 prefetch.
// No barriers inside the tap loop.
// ---------------------------------------------------------------------------
#define PP_STRIDE 536
#define XS_WORDS  (16 * PP_STRIDE)     // 8576 words = 34.3 KB
#define DYN_SMEM  (XS_WORDS * 4)

__global__ void __launch_bounds__(256, 3)
conv_mma_kernel(const float* __restrict__ X,
                const float* __restrict__ wt,
                float* __restrict__ out) {
    extern __shared__ __align__(16) float smem[];
    float* xs = smem;

    const int tid  = threadIdx.x;
    const int lane = tid & 31;
    const int wid  = tid >> 5;
    const int coh  = wid >> 2;           // co half (0/1)
    const int px0  = (wid & 3) * 32;     // warp pixel base

    const int b  = blockIdx.z;
    const int h0 = blockIdx.y * 2;
    const int w0 = blockIdx.x * 64;

    const float* Xb = X + (size_t)b * CIN_ * HW;
    // B fragment base for this warp (uint4 units): + coh block + lane
    const uint4* WbF = (const uint4*)(wt + (size_t)b * 36864) + coh * 64 + lane;

    // per-warp A base (word units): plane p=lane&3, column lane>>2
    const int a_fixed = (lane & 3) * PP_STRIDE
                      + ((px0 & 63) + (lane >> 2)) * 2;
    const int a_rbase = (px0 >> 6) * 132;

    float acc[2][4][4];
#pragma unroll
    for (int mt = 0; mt < 2; mt++)
#pragma unroll
        for (int nt = 0; nt < 4; nt++)
#pragma unroll
            for (int q = 0; q < 4; q++) acc[mt][nt][q] = 0.0f;

#pragma unroll
    for (int half = 0; half < 2; half++) {
        // ---- stage X half-tile (32 ci planes), tf32-rounded, pair-interleaved
        if (half == 1) __syncthreads();  // all warps done consuming half 0
        {
            const float* Xh = Xb + (size_t)(half * 32) * HW;
            for (int idx = tid; idx < 32 * 4 * 66; idx += 256) {
                const int row66 = idx / 66;          // ci*4 + r
                const int c     = idx - row66 * 66;
                const int ci    = row66 >> 2;
                const int r     = row66 & 3;
                const int gh    = h0 - 1 + r;
                const int gw    = w0 - 1 + c;
                float v = 0.0f;
                if ((unsigned)gh < (unsigned)HH && (unsigned)gw < (unsigned)WW)
                    v = Xh[(size_t)ci * HW + gh * WW + gw];
                const int pp = ((ci >> 3) << 2) | (ci & 3);
                const int s  = (ci >> 2) & 1;
                xs[pp * PP_STRIDE + r * 132 + c * 2 + s] = f2tf32f(v);
            }
        }
        __syncthreads();

        // ---- B prefetch pipeline (depth 2) over 36 flat steps ----
        const uint4* bh = WbF + (size_t)(half * 36) * 128;
        uint4 bA0 = __ldg(bh),       bA1 = __ldg(bh + 32);
        uint4 bB0 = __ldg(bh + 128), bB1 = __ldg(bh + 160);

#pragma unroll
        for (int t = 0; t < 9; t++) {
            const int kh = t / 3, kw = t - kh * 3;
            const float* abase = xs + a_fixed + (a_rbase + kh * 132) + kw * 2;

#pragma unroll
            for (int kk = 0; kk < 4; kk++) {
                uint4 cur0, cur1;
                if ((kk & 1) == 0) { cur0 = bA0; cur1 = bA1; }
                else               { cur0 = bB0; cur1 = bB1; }

                // A fragments: 4 LDS.64 (pairs (k, k+4) interleaved)
                const float* ap = abase + kk * (4 * PP_STRIDE);
                const uint2 q0 = *(const uint2*)(ap);        // (px,    k/k+4)
                const uint2 q1 = *(const uint2*)(ap + 16);   // (px+8,  ...)
                const uint2 q2 = *(const uint2*)(ap + 32);   // (px+16, ...)
                const uint2 q3 = *(const uint2*)(ap + 48);   // (px+24, ...)
                uint32_t a0[4] = { q0.x, q1.x, q0.y, q1.y };
                uint32_t a1[4] = { q2.x, q3.x, q2.y, q3.y };

                // prefetch step+2 into the slot just consumed
                const uint4* pf = bh + (size_t)(t * 4 + kk + 2) * 128;
                if ((kk & 1) == 0) { bA0 = __ldg(pf); bA1 = __ldg(pf + 32); }
                else               { bB0 = __ldg(pf); bB1 = __ldg(pf + 32); }

                MMA_OP(acc[0][0], a0, cur0.x, cur0.y);
                MMA_OP(acc[1][0], a1, cur0.x, cur0.y);
                MMA_OP(acc[0][1], a0, cur0.z, cur0.w);
                MMA_OP(acc[1][1], a1, cur0.z, cur0.w);
                MMA_OP(acc[0][2], a0, cur1.x, cur1.y);
                MMA_OP(acc[1][2], a1, cur1.x, cur1.y);
                MMA_OP(acc[0][3], a0, cur1.z, cur1.w);
                MMA_OP(acc[1][3], a1, cur1.z, cur1.w);
            }
        }
    }

    // ---- epilogue: direct store (full K accumulated per warp) ----
    const int co0 = coh * 32;
#pragma unroll
    for (int mt = 0; mt < 2; mt++) {
        const int pxm  = px0 + mt * 16 + (lane >> 2);
        const int h    = h0 + (pxm >> 6);
        const int wcol = w0 + (pxm & 63);
        float* o0 = out + (size_t)b * COUT_ * HW + (size_t)h * WW + wcol;
#pragma unroll
        for (int nt = 0; nt < 4; nt++) {
            const int co = co0 + nt * 8 + 2 * (lane & 3);
            float* p = o0 + (size_t)co * HW;
            p[0]      = acc[mt][nt][0];   // (px,    co)
            p[HW]     = acc[mt][nt][1];   // (px,    co+1)
            p[8]      = acc[mt][nt][2];   // (px+8,  co)
            p[HW + 8] = acc[mt][nt][3];   // (px+8,  co+1)
        }
    }
}

// ---------------------------------------------------------------------------
extern "C" void kernel_launch(void* const* d_in, const int* in_sizes, int n_in,
                              void* d_out, int out_size) {
    const float* X = (const float*)d_in[0];      // (16,64,256,256)
    const float* y = (const float*)d_in[1];      // (16,64)
    const float* w = (const float*)d_in[2];      // (64,64,3,3)
    float* out = (float*)d_out;                  // (16,64,256,256)

    float* wt;
    cudaGetSymbolAddress((void**)&wt, g_wt);

    cudaFuncSetAttribute(conv_mma_kernel,
                         cudaFuncAttributeMaxDynamicSharedMemorySize, DYN_SMEM);

    modw_kernel<<<dim3(COUT_, B_), CIN_>>>(w, y, wt);

    dim3 grid(WW / 64, HH / 2, B_);
    conv_mma_kernel<<<grid, 256, DYN_SMEM>>>(X, wt, out);
}